// round 7
// baseline (speedup 1.0000x reference)
#include <cuda_runtime.h>
#include <cuda_bf16.h>

// Problem constants (from reference init_kwargs)
#define T_FRAMES 96
#define H_DIM 720
#define W_DIM 1280
#define HW (H_DIM * W_DIM)        // 921600
#define HW4 (HW / 4)              // 230400 float4 groups per frame
#define NUM_NOISE 10

#define BLOCK_THREADS 160         // 230400 / 160 = 1440 blocks; 1440/148 = 9.73
                                  // -> per-SM split 10 vs 9 (+2.8% worst-SM excess,
                                  //    vs +16.7% with 900x256)

// With REFRACTORY_US == 0 the reference's idle mask is provably always true:
//   min_time = floor((cnt*DT)/DT) >= cnt-1  (each rounding <= 1 ulp, cnt <= 96)
//   ts holds only values <= cnt-1  ->  ts <= min_time always.
// Hence diff = x - st unconditionally and timesurface never affects output.
//
// Per-lane update:  diff==0 -> 127 ; diff>0 -> 255 ; diff<0 -> 0 ;
//                   st updated iff diff != 0 ; on-noise 255 then off-noise 0.
__device__ __forceinline__ float neuro_lane(float xi, float& sti,
                                            bool n_on, bool n_off)
{
    const float diff = xi - sti;
    float o;
    if (diff == 0.0f) {
        o = 127.0f;
    } else {
        o = (diff > 0.0f) ? 255.0f : 0.0f;
        sti = xi;
    }
    if (n_on)  o = 255.0f;
    if (n_off) o = 0.0f;
    return o;
}

// Build a 4-pixel noise nibble from a uint4 of 4-byte bools (int32 0/1 or
// float32 0.0/1.0 — nonzero bit pattern iff true).
__device__ __forceinline__ unsigned nibble_of(uint4 a)
{
    return (unsigned)(a.x != 0u) | ((unsigned)(a.y != 0u) << 1) |
           ((unsigned)(a.z != 0u) << 2) | ((unsigned)(a.w != 0u) << 3);
}

__global__ __launch_bounds__(BLOCK_THREADS, 12)
void Neuromorphizer_86457691668532_kernel(
    const float4* __restrict__ x,        // (T, H, W) as float4
    const float4* __restrict__ st_in,    // (H, W)
    const uint4*  __restrict__ on_n,     // (N_NOISE, H, W) 4B bools as uint4
    const uint4*  __restrict__ off_n,    // (N_NOISE, H, W) 4B bools as uint4
    float4* __restrict__ out)            // (T, H, W)
{
    const int p = blockIdx.x * BLOCK_THREADS + threadIdx.x;  // exact grid: no bounds check

    // ── Prologue: this thread's noise bits for all 10 planes -> two u64 regs.
    //    Bit 4*j+k = plane j, lane k. 20 independent streamed loads (high MLP).
    unsigned long long on64 = 0ull, off64 = 0ull;
    #pragma unroll
    for (int j = 0; j < NUM_NOISE; ++j) {
        const size_t base = (size_t)j * HW4 + p;
        on64  |= (unsigned long long)nibble_of(__ldcs(&on_n [base])) << (4 * j);
        off64 |= (unsigned long long)nibble_of(__ldcs(&off_n[base])) << (4 * j);
    }

    float4 st = st_in[p];

    unsigned sh = 0;   // = 4 * ((t+1) % 10), maintained incrementally

    #pragma unroll 4
    for (int t = 0; t < T_FRAMES; ++t) {
        sh += 4; if (sh >= 4 * NUM_NOISE) sh = 0;

        const size_t fb = (size_t)t * HW4 + p;
        const float4 xv = __ldcs(&x[fb]);

        const unsigned non = (unsigned)(on64  >> sh) & 0xFu;
        const unsigned nof = (unsigned)(off64 >> sh) & 0xFu;

        float4 o;
        o.x = neuro_lane(xv.x, st.x, (non & 1u) != 0u, (nof & 1u) != 0u);
        o.y = neuro_lane(xv.y, st.y, (non & 2u) != 0u, (nof & 2u) != 0u);
        o.z = neuro_lane(xv.z, st.z, (non & 4u) != 0u, (nof & 4u) != 0u);
        o.w = neuro_lane(xv.w, st.w, (non & 8u) != 0u, (nof & 8u) != 0u);

        __stcs(&out[fb], o);
    }
}

extern "C" void kernel_launch(void* const* d_in, const int* in_sizes, int n_in,
                              void* d_out, int out_size)
{
    // metadata order: tensor, state, timesurface, on_noise, off_noise
    // (timesurface d_in[2] is provably irrelevant — see comment in kernel.)
    const float4* x  = (const float4*)d_in[0];
    const float4* st = (const float4*)d_in[1];
    const uint4*  on_n  = (const uint4*)d_in[3];
    const uint4*  off_n = (const uint4*)d_in[4];
    float4* out = (float4*)d_out;

    const int blocks = HW4 / BLOCK_THREADS;    // 1440, exact
    Neuromorphizer_86457691668532_kernel<<<blocks, BLOCK_THREADS>>>(x, st, on_n, off_n, out);
}

// round 9
// speedup vs baseline: 1.0014x; 1.0014x over previous
#include <cuda_runtime.h>
#include <cuda_bf16.h>

// Problem constants (from reference init_kwargs)
#define T_FRAMES 96
#define H_DIM 720
#define W_DIM 1280
#define HW (H_DIM * W_DIM)        // 921600
#define HW4 (HW / 4)              // 230400 float4 groups per frame
#define NUM_NOISE 10

// With REFRACTORY_US == 0 the reference's idle mask is provably always true:
//   min_time = floor((cnt*DT)/DT) >= cnt-1  (each rounding <= 1 ulp, cnt <= 96)
//   ts holds only values <= cnt-1  ->  ts <= min_time always.
// Hence diff = x - st unconditionally and timesurface never affects output.
//
// Per-lane update:  diff==0 -> 127 ; diff>0 -> 255 ; diff<0 -> 0 ;
//                   st updated iff diff != 0 ; on-noise 255 then off-noise 0.
__device__ __forceinline__ float neuro_lane(float xi, float& sti,
                                            bool n_on, bool n_off)
{
    const float diff = xi - sti;
    float o;
    if (diff == 0.0f) {
        o = 127.0f;
    } else {
        o = (diff > 0.0f) ? 255.0f : 0.0f;
        sti = xi;
    }
    if (n_on)  o = 255.0f;
    if (n_off) o = 0.0f;
    return o;
}

// Build a 4-pixel noise nibble from a uint4 of 4-byte bools (int32 0/1 or
// float32 0.0/1.0 — nonzero bit pattern iff true).
__device__ __forceinline__ unsigned nibble_of(uint4 a)
{
    return (unsigned)(a.x != 0u) | ((unsigned)(a.y != 0u) << 1) |
           ((unsigned)(a.z != 0u) << 2) | ((unsigned)(a.w != 0u) << 3);
}

// 256 threads, min 8 blocks/SM -> forces regs <= 32 so 64 warps/SM are resident
// (R5 at 36 regs capped at 7 blocks/SM). 900 blocks -> one fully resident wave.
__global__ __launch_bounds__(256, 8)
void Neuromorphizer_86457691668532_kernel(
    const float4* __restrict__ x,        // (T, H, W) as float4
    const float4* __restrict__ st_in,    // (H, W)
    const uint4*  __restrict__ on_n,     // (N_NOISE, H, W) 4B bools as uint4
    const uint4*  __restrict__ off_n,    // (N_NOISE, H, W) 4B bools as uint4
    float4* __restrict__ out)            // (T, H, W)
{
    const int p = blockIdx.x * 256 + threadIdx.x;  // exact grid: no bounds check

    // ── Prologue: this thread's noise bits for all 10 planes -> two u64 regs.
    //    Bit 4*j+k = plane j, lane k. 20 independent streamed loads (high MLP).
    unsigned long long on64 = 0ull, off64 = 0ull;
    #pragma unroll
    for (int j = 0; j < NUM_NOISE; ++j) {
        const size_t base = (size_t)j * HW4 + p;
        on64  |= (unsigned long long)nibble_of(__ldcs(&on_n [base])) << (4 * j);
        off64 |= (unsigned long long)nibble_of(__ldcs(&off_n[base])) << (4 * j);
    }

    float4 st = st_in[p];

    unsigned sh = 0;   // = 4 * ((t+1) % 10), maintained incrementally

    // Unroll 8 (96 = 8*12 exact): 8 state-independent LDG.128s front-batched
    // per loop body -> MLP ~8 per thread, hiding DRAM latency.
    #pragma unroll 8
    for (int t = 0; t < T_FRAMES; ++t) {
        sh += 4; if (sh >= 4 * NUM_NOISE) sh = 0;

        const size_t fb = (size_t)t * HW4 + p;
        const float4 xv = __ldcs(&x[fb]);

        const unsigned non = (unsigned)(on64  >> sh) & 0xFu;
        const unsigned nof = (unsigned)(off64 >> sh) & 0xFu;

        float4 o;
        o.x = neuro_lane(xv.x, st.x, (non & 1u) != 0u, (nof & 1u) != 0u);
        o.y = neuro_lane(xv.y, st.y, (non & 2u) != 0u, (nof & 2u) != 0u);
        o.z = neuro_lane(xv.z, st.z, (non & 4u) != 0u, (nof & 4u) != 0u);
        o.w = neuro_lane(xv.w, st.w, (non & 8u) != 0u, (nof & 8u) != 0u);

        __stcs(&out[fb], o);
    }
}

extern "C" void kernel_launch(void* const* d_in, const int* in_sizes, int n_in,
                              void* d_out, int out_size)
{
    // metadata order: tensor, state, timesurface, on_noise, off_noise
    // (timesurface d_in[2] is provably irrelevant — see comment in kernel.)
    const float4* x  = (const float4*)d_in[0];
    const float4* st = (const float4*)d_in[1];
    const uint4*  on_n  = (const uint4*)d_in[3];
    const uint4*  off_n = (const uint4*)d_in[4];
    float4* out = (float4*)d_out;

    const int blocks = HW4 / 256;    // 900, exact
    Neuromorphizer_86457691668532_kernel<<<blocks, 256>>>(x, st, on_n, off_n, out);
}

// round 11
// speedup vs baseline: 1.0444x; 1.0429x over previous
#include <cuda_runtime.h>
#include <cuda_bf16.h>

// Problem constants (from reference init_kwargs)
#define T_FRAMES 96
#define H_DIM 720
#define W_DIM 1280
#define HW (H_DIM * W_DIM)        // 921600
#define HW4 (HW / 4)              // 230400 float4 groups per frame
#define NUM_NOISE 10

// Two exact algebraic reductions of the reference scan:
//  1) REFRACTORY_US == 0  =>  idle mask always true (min_time >= cnt-1 while
//     ts <= cnt-1), so timesurface never affects anything.
//  2) st_new = (diff != 0) ? x : st, but diff == 0 implies st == x already,
//     so st_t == x_t unconditionally. The scan degenerates to
//         out_t = g(x_t - x_{t-1}),  out_0 = g(x_0 - state_init)
//     with g: 0 -> 127, >0 -> 255, <0 -> 0, then on-noise 255, off-noise 0
//     (off wins). diff is computed exactly as the reference does.
__device__ __forceinline__ float neuro_lane(float xi, float prev,
                                            bool n_on, bool n_off)
{
    const float diff = xi - prev;
    float o = (diff == 0.0f) ? 127.0f : ((diff > 0.0f) ? 255.0f : 0.0f);
    if (n_on)  o = 255.0f;
    if (n_off) o = 0.0f;
    return o;
}

// Build a 4-pixel noise nibble from a uint4 of 4-byte bools (int32 0/1 or
// float32 0.0/1.0 — nonzero bit pattern iff true).
__device__ __forceinline__ unsigned nibble_of(uint4 a)
{
    return (unsigned)(a.x != 0u) | ((unsigned)(a.y != 0u) << 1) |
           ((unsigned)(a.z != 0u) << 2) | ((unsigned)(a.w != 0u) << 3);
}

// R5 geometry (empirical best): 900 blocks x 256 threads, no occupancy clamp.
__global__ __launch_bounds__(256)
void Neuromorphizer_86457691668532_kernel(
    const float4* __restrict__ x,        // (T, H, W) as float4
    const float4* __restrict__ st_in,    // (H, W) initial state
    const uint4*  __restrict__ on_n,     // (N_NOISE, H, W) 4B bools as uint4
    const uint4*  __restrict__ off_n,    // (N_NOISE, H, W) 4B bools as uint4
    float4* __restrict__ out)            // (T, H, W)
{
    const int p = blockIdx.x * 256 + threadIdx.x;  // exact grid: no bounds check

    // ── Prologue: this thread's noise bits for all 10 planes -> two u64 regs.
    //    Bit 4*j+k = plane j, lane k. 20 independent streamed loads (high MLP).
    unsigned long long on64 = 0ull, off64 = 0ull;
    #pragma unroll
    for (int j = 0; j < NUM_NOISE; ++j) {
        const size_t base = (size_t)j * HW4 + p;
        on64  |= (unsigned long long)nibble_of(__ldcs(&on_n [base])) << (4 * j);
        off64 |= (unsigned long long)nibble_of(__ldcs(&off_n[base])) << (4 * j);
    }

    float4 prev = st_in[p];

    unsigned sh = 0;   // = 4 * ((t+1) % 10), maintained incrementally

    #pragma unroll 4
    for (int t = 0; t < T_FRAMES; ++t) {
        sh += 4; if (sh >= 4 * NUM_NOISE) sh = 0;

        const size_t fb = (size_t)t * HW4 + p;
        const float4 xv = __ldcs(&x[fb]);

        const unsigned non = (unsigned)(on64  >> sh) & 0xFu;
        const unsigned nof = (unsigned)(off64 >> sh) & 0xFu;

        float4 o;
        o.x = neuro_lane(xv.x, prev.x, (non & 1u) != 0u, (nof & 1u) != 0u);
        o.y = neuro_lane(xv.y, prev.y, (non & 2u) != 0u, (nof & 2u) != 0u);
        o.z = neuro_lane(xv.z, prev.z, (non & 4u) != 0u, (nof & 4u) != 0u);
        o.w = neuro_lane(xv.w, prev.w, (non & 8u) != 0u, (nof & 8u) != 0u);

        __stcs(&out[fb], o);

        prev = xv;   // st_t == x_t (proven); pure register rename
    }
}

extern "C" void kernel_launch(void* const* d_in, const int* in_sizes, int n_in,
                              void* d_out, int out_size)
{
    // metadata order: tensor, state, timesurface, on_noise, off_noise
    // (timesurface d_in[2] is provably irrelevant — see comment in kernel.)
    const float4* x  = (const float4*)d_in[0];
    const float4* st = (const float4*)d_in[1];
    const uint4*  on_n  = (const uint4*)d_in[3];
    const uint4*  off_n = (const uint4*)d_in[4];
    float4* out = (float4*)d_out;

    const int blocks = HW4 / 256;    // 900, exact
    Neuromorphizer_86457691668532_kernel<<<blocks, 256>>>(x, st, on_n, off_n, out);
}